// round 11
// baseline (speedup 1.0000x reference)
#include <cuda_runtime.h>

// Bilinear resample: out[b,h,w] = bilinear(imgs[b], (w+dx, h+dy)) with
// zero-padding for out-of-bounds corners.
// imgs: (B,1024,1024,1) f32, dvfs: (B,1024,1024,2) f32, out: (B,1024,1024,1) f32.
//
// R1 inner code (2 px/thread, predicated @P gathers, float4/float2 I/O,
// streaming hints) with a 2D 64x8 block tile: 8 warps of one block cover 8
// adjacent image rows, so gathered img lines are reused in L1 (~8x) instead of
// bouncing to L2. Cuts average gather latency -> more in-flight DRAM bytes.

#define HH 1024
#define WW 1024
#define HW (HH * WW)

__device__ __forceinline__ float bilin_one(const float* __restrict__ img,
                                           int h, int w, float dx, float dy) {
    float fx = (float)w + dx;
    float fy = (float)h + dy;
    float x0f = floorf(fx);
    float y0f = floorf(fy);
    float wx = fx - x0f;
    float wy = fy - y0f;
    int x0 = (int)x0f;
    int y0 = (int)y0f;
    int x1 = x0 + 1;
    int y1 = y0 + 1;

    bool vx0 = (x0 >= 0) & (x0 < WW);
    bool vx1 = (x1 >= 0) & (x1 < WW);
    bool vy0 = (y0 >= 0) & (y0 < HH);
    bool vy1 = (y1 >= 0) & (y1 < HH);

    float v00 = 0.f, v01 = 0.f, v10 = 0.f, v11 = 0.f;
    if (vy0) {
        const float* row = img + (y0 << 10);
        if (vx0) v00 = __ldg(row + x0);
        if (vx1) v01 = __ldg(row + x1);
    }
    if (vy1) {
        const float* row = img + (y1 << 10);
        if (vx0) v10 = __ldg(row + x0);
        if (vx1) v11 = __ldg(row + x1);
    }

    float omx = 1.0f - wx;
    float omy = 1.0f - wy;
    float top = v00 * omx + v01 * wx;
    float bot = v10 * omx + v11 * wx;
    return top * omy + bot * wy;
}

__global__ void __launch_bounds__(256)
bilinear_kernel(const float* __restrict__ imgs,
                const float* __restrict__ dvfs,
                float* __restrict__ out) {
    // Block covers a 64(w) x 8(h) tile: threadIdx.x -> pixel pair in row,
    // threadIdx.y -> row within tile.
    int w = (blockIdx.x * 32 + threadIdx.x) * 2;
    int h = blockIdx.y * 8 + threadIdx.y;
    int b = blockIdx.z;

    const float* img = imgs + b * HW;
    size_t gidx = (size_t)b * HW + (h << 10) + w;

    // dvfs packed (x,y) interleaved: pixels idx, idx+1 -> 4 floats, 16B aligned.
    float4 d = __ldcs(reinterpret_cast<const float4*>(dvfs + gidx * 2));

    float r0 = bilin_one(img, h, w,     d.x, d.y);
    float r1 = bilin_one(img, h, w + 1, d.z, d.w);

    __stcs(reinterpret_cast<float2*>(out + gidx), make_float2(r0, r1));
}

extern "C" void kernel_launch(void* const* d_in, const int* in_sizes, int n_in,
                              void* d_out, int out_size) {
    const float* imgs = (const float*)d_in[0];
    const float* dvfs = (const float*)d_in[1];
    float* out = (float*)d_out;

    int B = out_size / HW;
    dim3 block(32, 8, 1);
    dim3 grid(WW / 64, HH / 8, B);    // (16, 128, B)
    bilinear_kernel<<<grid, block>>>(imgs, dvfs, out);
}

// round 13
// speedup vs baseline: 1.1687x; 1.1687x over previous
#include <cuda_runtime.h>

// Bilinear resample with zero-padding OOB corners.
// imgs: (B,1024,1024,1) f32, dvfs: (B,1024,1024,2) f32, out: (B,1024,1024,1) f32.
//
// Mapping: each thread processes pixel t AND pixel t + total/2 (far-apart
// halves). Each gather LDG spans only 32 consecutive px (~2 cache lines) ->
// minimal L1tex wavefronts, while the thread still has 8 independent gathers
// in flight (max MLP). Predicated @P gathers (cheap, exact zero-padding).

#define HH 1024
#define WW 1024
#define HW (HH * WW)

__device__ __forceinline__ float bilin_one(const float* __restrict__ img,
                                           int h, int w, float dx, float dy) {
    float fx = (float)w + dx;
    float fy = (float)h + dy;
    float x0f = floorf(fx);
    float y0f = floorf(fy);
    float wx = fx - x0f;
    float wy = fy - y0f;
    int x0 = (int)x0f;
    int y0 = (int)y0f;
    int x1 = x0 + 1;
    int y1 = y0 + 1;

    bool vx0 = (x0 >= 0) & (x0 < WW);
    bool vx1 = (x1 >= 0) & (x1 < WW);
    bool vy0 = (y0 >= 0) & (y0 < HH);
    bool vy1 = (y1 >= 0) & (y1 < HH);

    float v00 = 0.f, v01 = 0.f, v10 = 0.f, v11 = 0.f;
    if (vy0) {
        const float* row = img + (y0 << 10);
        if (vx0) v00 = __ldg(row + x0);
        if (vx1) v01 = __ldg(row + x1);
    }
    if (vy1) {
        const float* row = img + (y1 << 10);
        if (vx0) v10 = __ldg(row + x0);
        if (vx1) v11 = __ldg(row + x1);
    }

    float omx = 1.0f - wx;
    float omy = 1.0f - wy;
    float top = v00 * omx + v01 * wx;
    float bot = v10 * omx + v11 * wx;
    return top * omy + bot * wy;
}

__global__ void __launch_bounds__(256)
bilinear_kernel(const float* __restrict__ imgs,
                const float* __restrict__ dvfs,
                float* __restrict__ out,
                int half) {
    int t = blockIdx.x * blockDim.x + threadIdx.x;
    if (t >= half) return;

    int iA = t;               // pixel in first half
    int iB = t + half;        // pixel in second half (different images/rows)

    int wA = iA & (WW - 1);
    int hA = (iA >> 10) & (HH - 1);
    int bA = iA >> 20;
    int wB = iB & (WW - 1);
    int hB = (iB >> 10) & (HH - 1);
    int bB = iB >> 20;

    const float* imgA = imgs + bA * HW;
    const float* imgB = imgs + (size_t)bB * HW;

    // Two independent dvfs loads (each warp reads 256B contiguous, 2 lines).
    float2 dA = __ldcs(reinterpret_cast<const float2*>(dvfs) + iA);
    float2 dB = __ldcs(reinterpret_cast<const float2*>(dvfs) + iB);

    float rA = bilin_one(imgA, hA, wA, dA.x, dA.y);
    float rB = bilin_one(imgB, hB, wB, dB.x, dB.y);

    __stcs(out + iA, rA);
    __stcs(out + iB, rB);
}

extern "C" void kernel_launch(void* const* d_in, const int* in_sizes, int n_in,
                              void* d_out, int out_size) {
    const float* imgs = (const float*)d_in[0];
    const float* dvfs = (const float*)d_in[1];
    float* out = (float*)d_out;

    int half = out_size / 2;             // B*H*W / 2 threads
    int threads = 256;
    int blocks = (half + threads - 1) / threads;
    bilinear_kernel<<<blocks, threads>>>(imgs, dvfs, out, half);
}